// round 8
// baseline (speedup 1.0000x reference)
#include <cuda_runtime.h>
#include <cstdint>

#define C_DIM   128
#define N_COMP  16
#define BM      128
#define THREADS 512

// smem (192KB): X buf0 @ 0 (64KB), X buf1 @ 65536, W @ 131072 (64KB)
// tiles are [row][k] f32, 512B rows, 16B chunks XOR-swizzled by (row&7)
#define XBUF(p) ((uint32_t)(p) << 16)
#define OFF_W   131072u

__device__ __forceinline__ uint32_t smem_u32(const void* p) {
    uint32_t a;
    asm("{ .reg .u64 t; cvta.to.shared.u64 t, %1; cvt.u32.u64 %0, t; }"
        : "=r"(a) : "l"(p));
    return a;
}
__device__ __forceinline__ void bar_sync(int id) {
    asm volatile("bar.sync %0, 512;" :: "r"(id) : "memory");
}
__device__ __forceinline__ void bar_arrive(int id) {
    asm volatile("bar.arrive %0, 512;" :: "r"(id) : "memory");
}
__device__ __forceinline__ void ldmx4(uint32_t& r0, uint32_t& r1,
                                      uint32_t& r2, uint32_t& r3, uint32_t addr) {
    asm volatile("ldmatrix.sync.aligned.m8n8.x4.shared.b16 {%0,%1,%2,%3}, [%4];"
                 : "=r"(r0), "=r"(r1), "=r"(r2), "=r"(r3) : "r"(addr));
}
__device__ __forceinline__ void mma_tf32(float* c, const uint32_t* a,
                                         uint32_t b0, uint32_t b1) {
    asm volatile(
        "mma.sync.aligned.m16n8k8.row.col.f32.tf32.tf32.f32 "
        "{%0,%1,%2,%3}, {%4,%5,%6,%7}, {%8,%9}, {%0,%1,%2,%3};"
        : "+f"(c[0]), "+f"(c[1]), "+f"(c[2]), "+f"(c[3])
        : "r"(a[0]), "r"(a[1]), "r"(a[2]), "r"(a[3]), "r"(b0), "r"(b1));
}
__device__ __forceinline__ uint32_t cvt_tf32(float x) {
    uint32_t r;
    asm("cvt.rna.tf32.f32 %0, %1;" : "=r"(r) : "f"(x));
    return r;
}

// Warp-specialized persistent kernel, single-pass tf32.
// Warps 0-7: MMA + STG.  Warps 8-15: LDG + cvt.tf32 + swizzled STS.
// Each CTA owns a contiguous global-tile range; W re-staged on l change.
__global__ __launch_bounds__(THREADS, 1)
void tp_tf32(const float* __restrict__ x,
             const float* __restrict__ w,
             const float* __restrict__ pw,
             float* __restrict__ out,
             int n_nodes, int4 cum)
{
    extern __shared__ __align__(128) char smem[];
    const uint32_t sb = smem_u32(smem);

    const int tid  = threadIdx.x;
    const int lane = tid & 31;
    const int warp = tid >> 5;

    const int T = cum.w;
    const int t0 = (int)(((long long)blockIdx.x * T) / gridDim.x);
    const int t1 = (int)(((long long)(blockIdx.x + 1) * T) / gridDim.x);
    if (t0 >= t1) return;

    auto l_of = [&](int g) {
        return (g < cum.x) ? 0 : (g < cum.y) ? 1 : (g < cum.z) ? 2 : 3;
    };
    const int l_first = l_of(t0);
    const int l_last  = l_of(t1 - 1);

    // consumer fragment lane decomposition (tf32-via-ldmatrix.b16)
    const int wr = warp & 3;           // 32-row block
    const int wc = warp >> 2;          // 64-col block
    const int a_rowofs = (lane & 7) | (((lane >> 3) & 1) << 3);
    const int a_kh     = (lane >> 4) & 1;
    const int b_rowofs = (lane & 7) | (((lane >> 4) & 1) << 3);
    const int b_kh     = (lane >> 3) & 1;
    const int grp = lane >> 2;
    const int qid = lane & 3;

    uint32_t a_base[2]; int a_s[2];
    #pragma unroll
    for (int mt = 0; mt < 2; mt++) {
        int r = wr * 32 + mt * 16 + a_rowofs;
        a_base[mt] = (uint32_t)r << 9;     // row*512
        a_s[mt]    = r & 7;
    }
    uint32_t b_base[4]; int b_s[4];
    #pragma unroll
    for (int pr = 0; pr < 4; pr++) {
        int r = wc * 64 + pr * 16 + b_rowofs;
        b_base[pr] = OFF_W + ((uint32_t)r << 9);
        b_s[pr]    = r & 7;
    }

    const int ptid  = tid - 256;
    const int my_lr = ptid >> 5;
    const int my_v  = ptid & 31;
    const float4* x4 = (const float4*)x;

    for (int l = l_first; l <= l_last; l++) {
        const int cp = (l == 0) ? 0 : (l == 1) ? cum.x : (l == 2) ? cum.y : cum.z;
        const int ce = (l == 0) ? cum.x : (l == 1) ? cum.y : (l == 2) ? cum.z : cum.w;
        int s0 = t0 > cp ? t0 : cp;
        int s1 = t1 < ce ? t1 : ce;
        if (s0 >= s1) continue;
        const int n = s1 - s0;

        const int cl     = 2 * l + 1;
        const int mbase  = l * l;
        const int rows_l = n_nodes * cl;

        // ---- stage W[l]*pw -> tf32, [n][k] swizzled (all 512 threads) ----
        __syncthreads();
        {
            const float scale = __ldg(&pw[l]);
            const float* wp = w + (size_t)l * C_DIM * C_DIM;
            #pragma unroll
            for (int e = tid; e < C_DIM * C_DIM; e += THREADS) {
                int k = e >> 7, nn = e & 127;
                uint32_t tv = cvt_tf32(wp[e] * scale);
                uint32_t off = OFF_W + ((uint32_t)nn << 9)
                             + ((uint32_t)(((k >> 2) ^ (nn & 7))) << 4)
                             + (uint32_t)((k & 3) << 2);
                *(uint32_t*)(smem + off) = tv;
            }
        }
        __syncthreads();

        if (warp >= 8) {
            // ================= PRODUCER =================
            for (int i = 0; i < n; i++) {
                const int p = i & 1;
                const int row0 = (s0 + i - cp) * BM;
                const uint32_t xb = XBUF(p);
                #pragma unroll
                for (int wave = 0; wave < 2; wave++) {
                    float4 v[8];
                    #pragma unroll
                    for (int c = 0; c < 8; c++) {
                        int lr = wave * 64 + c * 8 + my_lr;
                        int r  = row0 + lr;
                        v[c] = make_float4(0.f, 0.f, 0.f, 0.f);
                        if (r < rows_l) {
                            int node = r / cl;
                            int m    = mbase + (r - node * cl);
                            v[c] = __ldg(x4 + ((size_t)node * N_COMP + m) * 32 + my_v);
                        }
                    }
                    if (wave == 0 && i >= 2) bar_sync(3 + p);
                    #pragma unroll
                    for (int c = 0; c < 8; c++) {
                        int lr = wave * 64 + c * 8 + my_lr;
                        uint4 t;
                        t.x = cvt_tf32(v[c].x);
                        t.y = cvt_tf32(v[c].y);
                        t.z = cvt_tf32(v[c].z);
                        t.w = cvt_tf32(v[c].w);
                        uint32_t off = xb + ((uint32_t)lr << 9)
                                     + ((uint32_t)((my_v ^ (lr & 7))) << 4);
                        *(uint4*)(smem + off) = t;
                    }
                }
                bar_arrive(1 + p);
            }
        } else {
            // ================= CONSUMER =================
            for (int i = 0; i < n; i++) {
                const int p = i & 1;
                const int row0 = (s0 + i - cp) * BM;
                const uint32_t xb = sb + XBUF(p);

                bar_sync(1 + p);

                float acc[2][8][4];
                #pragma unroll
                for (int mt = 0; mt < 2; mt++)
                    #pragma unroll
                    for (int n8 = 0; n8 < 8; n8++)
                        #pragma unroll
                        for (int j = 0; j < 4; j++) acc[mt][n8][j] = 0.f;

                #pragma unroll
                for (int ks = 0; ks < 16; ks++) {
                    uint32_t A[2][4];
                    #pragma unroll
                    for (int mt = 0; mt < 2; mt++) {
                        uint32_t ch = (uint32_t)((ks << 1) | a_kh);
                        uint32_t ad = xb + a_base[mt] + ((ch ^ (uint32_t)a_s[mt]) << 4);
                        ldmx4(A[mt][0], A[mt][1], A[mt][2], A[mt][3], ad);
                    }
                    uint32_t B[4][4];
                    #pragma unroll
                    for (int pr = 0; pr < 4; pr++) {
                        uint32_t ch = (uint32_t)((ks << 1) | b_kh);
                        uint32_t ad = sb + b_base[pr] + ((ch ^ (uint32_t)b_s[pr]) << 4);
                        ldmx4(B[pr][0], B[pr][1], B[pr][2], B[pr][3], ad);
                    }
                    #pragma unroll
                    for (int mt = 0; mt < 2; mt++)
                        #pragma unroll
                        for (int n8 = 0; n8 < 8; n8++) {
                            const int pr = n8 >> 1, q = (n8 & 1) * 2;
                            mma_tf32(acc[mt][n8], A[mt], B[pr][q], B[pr][q + 1]);
                        }
                }

                if (i + 3 <= n) bar_arrive(3 + p);   // skip last 2: keep barriers drained

                // ---- epilogue ----
                #pragma unroll
                for (int mt = 0; mt < 2; mt++) {
                    #pragma unroll
                    for (int h = 0; h < 2; h++) {
                        int r = row0 + wr * 32 + mt * 16 + grp + h * 8;
                        if (r < rows_l) {
                            int node = r / cl;
                            int m    = mbase + (r - node * cl);
                            float* orow = out + ((size_t)node * N_COMP + m) * C_DIM
                                              + wc * 64 + qid * 2;
                            #pragma unroll
                            for (int n8 = 0; n8 < 8; n8++) {
                                float2 v2 = make_float2(acc[mt][n8][h * 2],
                                                        acc[mt][n8][h * 2 + 1]);
                                *(float2*)(orow + n8 * 8) = v2;
                            }
                        }
                    }
                }
            }
        }
    }
}

extern "C" void kernel_launch(void* const* d_in, const int* in_sizes, int n_in,
                              void* d_out, int out_size) {
    const float* x  = (const float*)d_in[0];
    const float* w  = (const float*)d_in[1];
    const float* pw = (const float*)d_in[2];
    float* out = (float*)d_out;

    const int n_nodes = in_sizes[0] / (N_COMP * C_DIM);

    int dev = 0, nsm = 148;
    cudaGetDevice(&dev);
    cudaDeviceGetAttribute(&nsm, cudaDevAttrMultiProcessorCount, dev);

    int t[4], c = 0;
    int4 cum;
    for (int l = 0; l < 4; l++)
        t[l] = (n_nodes * (2 * l + 1) + BM - 1) / BM;
    cum.x = t[0];
    cum.y = cum.x + t[1];
    cum.z = cum.y + t[2];
    cum.w = cum.z + t[3];
    (void)c;

    size_t smem_bytes = 196608;   // 192KB
    cudaFuncSetAttribute(tp_tf32,
                         cudaFuncAttributeMaxDynamicSharedMemorySize,
                         (int)smem_bytes);

    tp_tf32<<<nsm, THREADS, smem_bytes>>>(x, w, pw, out, n_nodes, cum);
}

// round 9
// speedup vs baseline: 1.0270x; 1.0270x over previous
#include <cuda_runtime.h>
#include <cstdint>

#define C_DIM   128
#define N_COMP  16
#define BM      128
#define THREADS 512

// smem (192KB): X buf0 @ 0 (64KB), X buf1 @ 65536, W @ 131072 (64KB)
// tiles are [row][k] f32, 512B rows, 16B chunks XOR-swizzled by (row&7)
#define XBUF(p) ((uint32_t)(p) << 16)
#define OFF_W   131072u

__device__ __forceinline__ uint32_t smem_u32(const void* p) {
    uint32_t a;
    asm("{ .reg .u64 t; cvta.to.shared.u64 t, %1; cvt.u32.u64 %0, t; }"
        : "=r"(a) : "l"(p));
    return a;
}
__device__ __forceinline__ void bar_sync(int id) {
    asm volatile("bar.sync %0, 512;" :: "r"(id) : "memory");
}
__device__ __forceinline__ void bar_arrive(int id) {
    asm volatile("bar.arrive %0, 512;" :: "r"(id) : "memory");
}
__device__ __forceinline__ void ldmx4(uint32_t& r0, uint32_t& r1,
                                      uint32_t& r2, uint32_t& r3, uint32_t addr) {
    asm volatile("ldmatrix.sync.aligned.m8n8.x4.shared.b16 {%0,%1,%2,%3}, [%4];"
                 : "=r"(r0), "=r"(r1), "=r"(r2), "=r"(r3) : "r"(addr));
}
__device__ __forceinline__ void mma_tf32(float* c, const uint32_t* a,
                                         uint32_t b0, uint32_t b1) {
    asm volatile(
        "mma.sync.aligned.m16n8k8.row.col.f32.tf32.tf32.f32 "
        "{%0,%1,%2,%3}, {%4,%5,%6,%7}, {%8,%9}, {%0,%1,%2,%3};"
        : "+f"(c[0]), "+f"(c[1]), "+f"(c[2]), "+f"(c[3])
        : "r"(a[0]), "r"(a[1]), "r"(a[2]), "r"(a[3]), "r"(b0), "r"(b1));
}
__device__ __forceinline__ uint32_t cvt_tf32(float x) {
    uint32_t r;
    asm("cvt.rna.tf32.f32 %0, %1;" : "=r"(r) : "f"(x));
    return r;
}

// Warp-specialized persistent tf32 kernel.
// Warps 0-7: MMA + STG.  Warps 8-15: LDG + cvt.tf32 + swizzled STS.
// Contiguous balanced tile split; W re-staged on l change.
__global__ __launch_bounds__(THREADS, 1)
void tp_tf32b(const float* __restrict__ x,
              const float* __restrict__ w,
              const float* __restrict__ pw,
              float* __restrict__ out,
              int n_nodes, int4 cum)
{
    extern __shared__ __align__(128) char smem[];
    const uint32_t sb = smem_u32(smem);

    const int tid  = threadIdx.x;
    const int lane = tid & 31;
    const int warp = tid >> 5;

    const int T = cum.w;
    const int t0 = (int)(((long long)blockIdx.x * T) / gridDim.x);
    const int t1 = (int)(((long long)(blockIdx.x + 1) * T) / gridDim.x);
    if (t0 >= t1) return;

    auto l_of = [&](int g) {
        return (g < cum.x) ? 0 : (g < cum.y) ? 1 : (g < cum.z) ? 2 : 3;
    };
    const int l_first = l_of(t0);
    const int l_last  = l_of(t1 - 1);

    // consumer fragment lane decomposition (tf32-via-ldmatrix.b16)
    const int wr = warp & 3;           // 32-row block
    const int wc = warp >> 2;          // 64-col block
    const int a_rowofs = (lane & 7) | (((lane >> 3) & 1) << 3);
    const int a_kh     = (lane >> 4) & 1;
    const int b_rowofs = (lane & 7) | (((lane >> 4) & 1) << 3);
    const int b_kh     = (lane >> 3) & 1;
    const int grp = lane >> 2;
    const int qid = lane & 3;

    uint32_t a_base[2];
    #pragma unroll
    for (int mt = 0; mt < 2; mt++) {
        int r = wr * 32 + mt * 16 + a_rowofs;
        a_base[mt] = ((uint32_t)r << 9) | ((uint32_t)(r & 7) << 4) | (uint32_t)a_kh;
        // low 4 bits stash swizzle key + kh:   addr = (base&~15) ... decoded below
    }
    uint32_t b_base[4];
    #pragma unroll
    for (int pr = 0; pr < 4; pr++) {
        int r = wc * 64 + pr * 16 + b_rowofs;
        b_base[pr] = ((uint32_t)r << 9) | ((uint32_t)(r & 7) << 4) | (uint32_t)b_kh;
    }

    const int ptid  = tid - 256;
    const int my_lr = ptid >> 5;
    const int my_v  = ptid & 31;
    const float4* x4 = (const float4*)x;

    for (int l = l_first; l <= l_last; l++) {
        const int cp = (l == 0) ? 0 : (l == 1) ? cum.x : (l == 2) ? cum.y : cum.z;
        const int ce = (l == 0) ? cum.x : (l == 1) ? cum.y : (l == 2) ? cum.z : cum.w;
        int s0 = t0 > cp ? t0 : cp;
        int s1 = t1 < ce ? t1 : ce;
        if (s0 >= s1) continue;
        const int n = s1 - s0;

        const int cl     = 2 * l + 1;
        const int mbase  = l * l;
        const int rows_l = n_nodes * cl;

        // ---- stage W[l]*pw -> tf32, [n][k] swizzled (all 512 threads) ----
        __syncthreads();
        {
            const float scale = __ldg(&pw[l]);
            const float* wp = w + (size_t)l * C_DIM * C_DIM;
            #pragma unroll
            for (int e = tid; e < C_DIM * C_DIM; e += THREADS) {
                int k = e >> 7, nn = e & 127;
                uint32_t tv = cvt_tf32(wp[e] * scale);
                uint32_t off = OFF_W + ((uint32_t)nn << 9)
                             + ((uint32_t)(((k >> 2) ^ (nn & 7))) << 4)
                             + (uint32_t)((k & 3) << 2);
                *(uint32_t*)(smem + off) = tv;
            }
        }
        __syncthreads();

        if (warp >= 8) {
            // ================= PRODUCER =================
            for (int i = 0; i < n; i++) {
                const int p = i & 1;
                const int row0 = (s0 + i - cp) * BM;
                const uint32_t xb = XBUF(p);
                #pragma unroll
                for (int wave = 0; wave < 2; wave++) {
                    // load 8 rows' worth, convert in regs, THEN wait, then STS
                    uint4 t[8];
                    #pragma unroll
                    for (int c = 0; c < 8; c++) {
                        int lr = wave * 64 + c * 8 + my_lr;
                        int r  = row0 + lr;
                        float4 v = make_float4(0.f, 0.f, 0.f, 0.f);
                        if (r < rows_l) {
                            int node = r / cl;
                            int m    = mbase + (r - node * cl);
                            v = __ldg(x4 + ((size_t)node * N_COMP + m) * 32 + my_v);
                        }
                        t[c].x = cvt_tf32(v.x);
                        t[c].y = cvt_tf32(v.y);
                        t[c].z = cvt_tf32(v.z);
                        t[c].w = cvt_tf32(v.w);
                    }
                    if (wave == 0 && i >= 2) bar_sync(3 + p);
                    #pragma unroll
                    for (int c = 0; c < 8; c++) {
                        int lr = wave * 64 + c * 8 + my_lr;
                        uint32_t off = xb + ((uint32_t)lr << 9)
                                     + ((uint32_t)((my_v ^ (lr & 7))) << 4);
                        *(uint4*)(smem + off) = t[c];
                    }
                }
                bar_arrive(1 + p);
            }
        } else {
            // ================= CONSUMER =================
            for (int i = 0; i < n; i++) {
                const int p = i & 1;
                const int row0 = (s0 + i - cp) * BM;
                const uint32_t xb = sb + XBUF(p);

                bar_sync(1 + p);

                float acc[2][8][4];
                #pragma unroll
                for (int mt = 0; mt < 2; mt++)
                    #pragma unroll
                    for (int n8 = 0; n8 < 8; n8++)
                        #pragma unroll
                        for (int j = 0; j < 4; j++) acc[mt][n8][j] = 0.f;

                #pragma unroll 4
                for (int ks = 0; ks < 16; ks++) {
                    uint32_t A[2][4];
                    #pragma unroll
                    for (int mt = 0; mt < 2; mt++) {
                        uint32_t key = a_base[mt];
                        uint32_t ch  = (uint32_t)((ks << 1)) | (key & 1);
                        uint32_t ad  = xb + (key & 0xFFFFFE00u)
                                     + (((ch ^ ((key >> 4) & 7u))) << 4);
                        ldmx4(A[mt][0], A[mt][1], A[mt][2], A[mt][3], ad);
                    }
                    #pragma unroll
                    for (int pr = 0; pr < 4; pr++) {
                        uint32_t key = b_base[pr];
                        uint32_t ch  = (uint32_t)((ks << 1)) | (key & 1);
                        uint32_t ad  = sb + OFF_W + (key & 0xFFFFFE00u)
                                     + (((ch ^ ((key >> 4) & 7u))) << 4);
                        uint32_t B0, B1, B2, B3;
                        ldmx4(B0, B1, B2, B3, ad);
                        #pragma unroll
                        for (int mt = 0; mt < 2; mt++) {
                            mma_tf32(acc[mt][2 * pr],     A[mt], B0, B1);
                            mma_tf32(acc[mt][2 * pr + 1], A[mt], B2, B3);
                        }
                    }
                }

                if (i + 3 <= n) bar_arrive(3 + p);

                // ---- epilogue ----
                #pragma unroll
                for (int mt = 0; mt < 2; mt++) {
                    #pragma unroll
                    for (int h = 0; h < 2; h++) {
                        int r = row0 + wr * 32 + mt * 16 + grp + h * 8;
                        if (r < rows_l) {
                            int node = r / cl;
                            int m    = mbase + (r - node * cl);
                            float* orow = out + ((size_t)node * N_COMP + m) * C_DIM
                                              + wc * 64 + qid * 2;
                            #pragma unroll
                            for (int n8 = 0; n8 < 8; n8++) {
                                float2 v2 = make_float2(acc[mt][n8][h * 2],
                                                        acc[mt][n8][h * 2 + 1]);
                                *(float2*)(orow + n8 * 8) = v2;
                            }
                        }
                    }
                }
            }
        }
    }
}

extern "C" void kernel_launch(void* const* d_in, const int* in_sizes, int n_in,
                              void* d_out, int out_size) {
    const float* x  = (const float*)d_in[0];
    const float* w  = (const float*)d_in[1];
    const float* pw = (const float*)d_in[2];
    float* out = (float*)d_out;

    const int n_nodes = in_sizes[0] / (N_COMP * C_DIM);

    int dev = 0, nsm = 148;
    cudaGetDevice(&dev);
    cudaDeviceGetAttribute(&nsm, cudaDevAttrMultiProcessorCount, dev);

    int t[4];
    int4 cum;
    for (int l = 0; l < 4; l++)
        t[l] = (n_nodes * (2 * l + 1) + BM - 1) / BM;
    cum.x = t[0];
    cum.y = cum.x + t[1];
    cum.z = cum.y + t[2];
    cum.w = cum.z + t[3];

    size_t smem_bytes = 196608;   // 192KB
    cudaFuncSetAttribute(tp_tf32b,
                         cudaFuncAttributeMaxDynamicSharedMemorySize,
                         (int)smem_bytes);

    tp_tf32b<<<nsm, THREADS, smem_bytes>>>(x, w, pw, out, n_nodes, cum);
}

// round 10
// speedup vs baseline: 2.1852x; 2.1277x over previous
#include <cuda_runtime.h>
#include <cuda_bf16.h>
#include <cstdint>

#define C_DIM   128
#define N_COMP  16
#define BM      128
#define THREADS 768   // warps 0-15 consumers, 16-23 producers

// smem (192KB):
//   X buf0: Xh @ 0      Xl @ 32768
//   X buf1: Xh @ 65536  Xl @ 98304
//   Wh @ 131072, Wl @ 163840
#define XBUF(p)  ((uint32_t)(p) << 16)
#define OFF_XL   32768u
#define OFF_WH   131072u
#define OFF_WL   163840u
#define HALF     16384u

__device__ __forceinline__ uint32_t smem_u32(const void* p) {
    uint32_t a;
    asm("{ .reg .u64 t; cvta.to.shared.u64 t, %1; cvt.u32.u64 %0, t; }"
        : "=r"(a) : "l"(p));
    return a;
}
__device__ __forceinline__ void bar_sync(int id) {
    asm volatile("bar.sync %0, %1;" :: "r"(id), "r"(THREADS) : "memory");
}
__device__ __forceinline__ void bar_arrive(int id) {
    asm volatile("bar.arrive %0, %1;" :: "r"(id), "r"(THREADS) : "memory");
}
__device__ __forceinline__ void ldmx4(uint32_t& r0, uint32_t& r1,
                                      uint32_t& r2, uint32_t& r3, uint32_t addr) {
    asm volatile("ldmatrix.sync.aligned.m8n8.x4.shared.b16 {%0,%1,%2,%3}, [%4];"
                 : "=r"(r0), "=r"(r1), "=r"(r2), "=r"(r3) : "r"(addr));
}
__device__ __forceinline__ void mma16816(float* c, const uint32_t* a,
                                         uint32_t b0, uint32_t b1) {
    asm volatile(
        "mma.sync.aligned.m16n8k16.row.col.f32.bf16.bf16.f32 "
        "{%0,%1,%2,%3}, {%4,%5,%6,%7}, {%8,%9}, {%0,%1,%2,%3};"
        : "+f"(c[0]), "+f"(c[1]), "+f"(c[2]), "+f"(c[3])
        : "r"(a[0]), "r"(a[1]), "r"(a[2]), "r"(a[3]), "r"(b0), "r"(b1));
}

// swizzled byte offset within a 128row x 128k bf16 tile (two 16KB k-halves,
// 128B rows, 16B chunks XOR-permuted by row&7)
__device__ __forceinline__ uint32_t swz_off(int row, int k) {
    return ((uint32_t)(k >> 6) << 14) + ((uint32_t)row << 7)
         + ((uint32_t)((((k & 63) >> 3) ^ (row & 7))) << 4)
         + (uint32_t)((k & 7) << 1);
}

// exact magic division by cl = 2l+1 for all uint32 r
__device__ __forceinline__ uint32_t div_cl(uint32_t r, uint64_t M, int S) {
    return (uint32_t)(((uint64_t)r * M) >> S);
}

// Warp-specialized persistent bf16 3-pass kernel.
// Consumers (warps 0-15): 32x32 tiles, MMA + STG. Producers (16-23): LDG +
// bf16 hi/lo split + swizzled STS. Contiguous balanced tile split; W per l.
__global__ __launch_bounds__(THREADS, 1)
void tp_ws2(const float* __restrict__ x,
            const float* __restrict__ w,
            const float* __restrict__ pw,
            float* __restrict__ out,
            int n_nodes, int4 cum)
{
    extern __shared__ __align__(128) char smem[];
    const uint32_t sb = smem_u32(smem);

    const int tid  = threadIdx.x;
    const int lane = tid & 31;
    const int warp = tid >> 5;

    const int T  = cum.w;
    const int t0 = (int)(((long long)blockIdx.x * T) / gridDim.x);
    const int t1 = (int)(((long long)(blockIdx.x + 1) * T) / gridDim.x);
    if (t0 >= t1) return;

    auto l_of = [&](int g) {
        return (g < cum.x) ? 0 : (g < cum.y) ? 1 : (g < cum.z) ? 2 : 3;
    };
    const int l_first = l_of(t0);
    const int l_last  = l_of(t1 - 1);

    // consumer lane decomposition (32x32 warp tile)
    const int wr = warp & 3;           // 32-row block
    const int wc = warp >> 2;          // 32-col block
    const int a_hi = lane >> 4;
    int a_row[2], a_s[2];
    #pragma unroll
    for (int mt = 0; mt < 2; mt++) {
        a_row[mt] = wr * 32 + mt * 16 + (lane & 15);
        a_s[mt]   = a_row[mt] & 7;
    }
    const int bg   = lane >> 3;
    const int b_hi = bg & 1;
    int b_row[2], b_s[2];
    #pragma unroll
    for (int nt = 0; nt < 2; nt++) {
        b_row[nt] = wc * 32 + nt * 16 + ((bg >> 1) * 8) + (lane & 7);
        b_s[nt]   = b_row[nt] & 7;
    }
    const int grp = lane >> 2;
    const int qid = lane & 3;

    const int ptid  = tid - 512;       // producer-local
    const int my_lr = ptid >> 5;
    const int my_v  = ptid & 31;
    const float4* x4 = (const float4*)x;

    for (int l = l_first; l <= l_last; l++) {
        const int cp = (l == 0) ? 0 : (l == 1) ? cum.x : (l == 2) ? cum.y : cum.z;
        const int ce = (l == 0) ? cum.x : (l == 1) ? cum.y : (l == 2) ? cum.z : cum.w;
        int s0 = t0 > cp ? t0 : cp;
        int s1 = t1 < ce ? t1 : ce;
        if (s0 >= s1) continue;
        const int n = s1 - s0;

        const int cl     = 2 * l + 1;
        const int mbase  = l * l;
        const int rows_l = n_nodes * cl;
        const uint64_t M = (l == 0) ? 1ull : (l == 1) ? 0xAAAAAAABull
                         : (l == 2) ? 0xCCCCCCCDull : 0x92492493ull;
        const int S = (l == 0) ? 0 : (l == 1) ? 33 : 34;

        // ---- stage W[l]*pw -> bf16 hi/lo (all threads, once per segment) ----
        __syncthreads();
        {
            const float scale = __ldg(&pw[l]);
            const float* wp = w + (size_t)l * C_DIM * C_DIM;
            #pragma unroll
            for (int e = tid; e < C_DIM * C_DIM; e += THREADS) {
                int k = e >> 7, nn = e & 127;
                float v = wp[e] * scale;
                __nv_bfloat16 h  = __float2bfloat16(v);
                __nv_bfloat16 lo = __float2bfloat16(v - __bfloat162float(h));
                uint32_t off = swz_off(nn, k);
                *(__nv_bfloat16*)(smem + OFF_WH + off) = h;
                *(__nv_bfloat16*)(smem + OFF_WL + off) = lo;
            }
        }
        __syncthreads();

        if (warp >= 16) {
            // ================= PRODUCER =================
            for (int i = 0; i < n; i++) {
                const int p = i & 1;
                const int row0 = (s0 + i - cp) * BM;
                const uint32_t xb = XBUF(p);
                #pragma unroll
                for (int wave = 0; wave < 2; wave++) {
                    float4 v[8];
                    #pragma unroll
                    for (int c = 0; c < 8; c++) {
                        int lr = wave * 64 + c * 8 + my_lr;
                        int r  = row0 + lr;
                        v[c] = make_float4(0.f, 0.f, 0.f, 0.f);
                        if (r < rows_l) {
                            uint32_t node = div_cl((uint32_t)r, M, S);
                            uint32_t m    = (uint32_t)mbase + ((uint32_t)r - node * cl);
                            v[c] = __ldg(x4 + ((size_t)node * N_COMP + m) * 32 + my_v);
                        }
                    }
                    if (wave == 0 && i >= 2) bar_sync(3 + p);
                    #pragma unroll
                    for (int c = 0; c < 8; c++) {
                        int lr = wave * 64 + c * 8 + my_lr;
                        float4 f = v[c];
                        __nv_bfloat162 h0 = __floats2bfloat162_rn(f.x, f.y);
                        __nv_bfloat162 h1 = __floats2bfloat162_rn(f.z, f.w);
                        __nv_bfloat162 l0 = __floats2bfloat162_rn(
                            f.x - __bfloat162float(__low2bfloat16(h0)),
                            f.y - __bfloat162float(__high2bfloat16(h0)));
                        __nv_bfloat162 l1 = __floats2bfloat162_rn(
                            f.z - __bfloat162float(__low2bfloat16(h1)),
                            f.w - __bfloat162float(__high2bfloat16(h1)));
                        uint32_t off = xb + swz_off(lr, my_v * 4);
                        uint2 uh, ul;
                        uh.x = *(uint32_t*)&h0; uh.y = *(uint32_t*)&h1;
                        ul.x = *(uint32_t*)&l0; ul.y = *(uint32_t*)&l1;
                        *(uint2*)(smem + off)          = uh;
                        *(uint2*)(smem + OFF_XL + off) = ul;
                    }
                }
                bar_arrive(1 + p);
            }
        } else {
            // ================= CONSUMER =================
            for (int i = 0; i < n; i++) {
                const int p = i & 1;
                const int row0 = (s0 + i - cp) * BM;
                const uint32_t xb = sb + XBUF(p);

                bar_sync(1 + p);

                float acc[2][4][4];
                #pragma unroll
                for (int mt = 0; mt < 2; mt++)
                    #pragma unroll
                    for (int n8 = 0; n8 < 4; n8++)
                        #pragma unroll
                        for (int j = 0; j < 4; j++) acc[mt][n8][j] = 0.f;

                #pragma unroll
                for (int ks = 0; ks < 8; ks++) {
                    const uint32_t hoff = (ks & 4) ? HALF : 0u;
                    const int c0 = (ks & 3) * 2;

                    uint32_t Ah[2][4], Al[2][4];
                    #pragma unroll
                    for (int mt = 0; mt < 2; mt++) {
                        uint32_t a = xb + hoff + (uint32_t)(a_row[mt] << 7)
                                   + (uint32_t)((((c0 | a_hi) ^ a_s[mt])) << 4);
                        ldmx4(Ah[mt][0], Ah[mt][1], Ah[mt][2], Ah[mt][3], a);
                        ldmx4(Al[mt][0], Al[mt][1], Al[mt][2], Al[mt][3], a + OFF_XL);
                    }
                    uint32_t Bh[2][4], Bl[2][4];
                    #pragma unroll
                    for (int nt = 0; nt < 2; nt++) {
                        uint32_t b = sb + hoff + (uint32_t)(b_row[nt] << 7)
                                   + (uint32_t)((((c0 | b_hi) ^ b_s[nt])) << 4);
                        ldmx4(Bh[nt][0], Bh[nt][1], Bh[nt][2], Bh[nt][3], b + OFF_WH);
                        ldmx4(Bl[nt][0], Bl[nt][1], Bl[nt][2], Bl[nt][3], b + OFF_WL);
                    }
                    #pragma unroll
                    for (int mt = 0; mt < 2; mt++)
                        #pragma unroll
                        for (int n8 = 0; n8 < 4; n8++) {
                            const int nt = n8 >> 1, q = (n8 & 1) * 2;
                            mma16816(acc[mt][n8], Ah[mt], Bh[nt][q], Bh[nt][q + 1]);
                            mma16816(acc[mt][n8], Al[mt], Bh[nt][q], Bh[nt][q + 1]);
                            mma16816(acc[mt][n8], Ah[mt], Bl[nt][q], Bl[nt][q + 1]);
                        }
                }

                if (i + 3 <= n) bar_arrive(3 + p);

                // ---- epilogue ----
                #pragma unroll
                for (int mt = 0; mt < 2; mt++) {
                    #pragma unroll
                    for (int h = 0; h < 2; h++) {
                        int r = row0 + wr * 32 + mt * 16 + grp + h * 8;
                        if (r < rows_l) {
                            uint32_t node = div_cl((uint32_t)r, M, S);
                            uint32_t m    = (uint32_t)mbase + ((uint32_t)r - node * cl);
                            float* orow = out + ((size_t)node * N_COMP + m) * C_DIM
                                              + wc * 32 + qid * 2;
                            #pragma unroll
                            for (int n8 = 0; n8 < 4; n8++) {
                                float2 v2 = make_float2(acc[mt][n8][h * 2],
                                                        acc[mt][n8][h * 2 + 1]);
                                *(float2*)(orow + n8 * 8) = v2;
                            }
                        }
                    }
                }
            }
        }
    }
}

extern "C" void kernel_launch(void* const* d_in, const int* in_sizes, int n_in,
                              void* d_out, int out_size) {
    const float* x  = (const float*)d_in[0];
    const float* w  = (const float*)d_in[1];
    const float* pw = (const float*)d_in[2];
    float* out = (float*)d_out;

    const int n_nodes = in_sizes[0] / (N_COMP * C_DIM);

    int dev = 0, nsm = 148;
    cudaGetDevice(&dev);
    cudaDeviceGetAttribute(&nsm, cudaDevAttrMultiProcessorCount, dev);

    int t[4];
    int4 cum;
    for (int l = 0; l < 4; l++)
        t[l] = (n_nodes * (2 * l + 1) + BM - 1) / BM;
    cum.x = t[0];
    cum.y = cum.x + t[1];
    cum.z = cum.y + t[2];
    cum.w = cum.z + t[3];

    size_t smem_bytes = 196608;   // 192KB
    cudaFuncSetAttribute(tp_ws2,
                         cudaFuncAttributeMaxDynamicSharedMemorySize,
                         (int)smem_bytes);

    tp_ws2<<<nsm, THREADS, smem_bytes>>>(x, w, pw, out, n_nodes, cum);
}

// round 12
// speedup vs baseline: 2.9744x; 1.3612x over previous
#include <cuda_runtime.h>
#include <cuda_fp16.h>
#include <cstdint>

#define C_DIM   128
#define N_COMP  16
#define BM      128
#define THREADS 768   // warps 0-15 consumers, 16-23 producers
#define NBUF    4

// smem (160KB): X ring: 4 x 32KB fp16 tiles @ p*32768; W @ 131072 (32KB)
#define XBUF(p)  ((uint32_t)(p) << 15)
#define OFF_W    131072u
#define HALF     16384u   // one k-half of a 128-row fp16 tile (128 rows * 128B)

__device__ __forceinline__ uint32_t smem_u32(const void* p) {
    uint32_t a;
    asm("{ .reg .u64 t; cvta.to.shared.u64 t, %1; cvt.u32.u64 %0, t; }"
        : "=r"(a) : "l"(p));
    return a;
}
__device__ __forceinline__ void bar_sync(int id) {
    asm volatile("bar.sync %0, %1;" :: "r"(id), "r"(THREADS) : "memory");
}
__device__ __forceinline__ void bar_arrive(int id) {
    asm volatile("bar.arrive %0, %1;" :: "r"(id), "r"(THREADS) : "memory");
}
__device__ __forceinline__ void ldmx4(uint32_t& r0, uint32_t& r1,
                                      uint32_t& r2, uint32_t& r3, uint32_t addr) {
    asm volatile("ldmatrix.sync.aligned.m8n8.x4.shared.b16 {%0,%1,%2,%3}, [%4];"
                 : "=r"(r0), "=r"(r1), "=r"(r2), "=r"(r3) : "r"(addr));
}
__device__ __forceinline__ void mma_f16(float* c, const uint32_t* a,
                                        uint32_t b0, uint32_t b1) {
    asm volatile(
        "mma.sync.aligned.m16n8k16.row.col.f32.f16.f16.f32 "
        "{%0,%1,%2,%3}, {%4,%5,%6,%7}, {%8,%9}, {%0,%1,%2,%3};"
        : "+f"(c[0]), "+f"(c[1]), "+f"(c[2]), "+f"(c[3])
        : "r"(a[0]), "r"(a[1]), "r"(a[2]), "r"(a[3]), "r"(b0), "r"(b1));
}

// swizzled byte offset within a 128row x 128k fp16 tile: two 16KB k-halves
// (64 k each, 128B rows), 16B chunks XOR-permuted by row&7
__device__ __forceinline__ uint32_t swz_off(int row, int k) {
    return ((uint32_t)(k >> 6) << 14) + ((uint32_t)row << 7)
         + ((uint32_t)((((k & 63) >> 3) ^ (row & 7))) << 4)
         + (uint32_t)((k & 7) << 1);
}

// exact magic division by cl = 2l+1
__device__ __forceinline__ uint32_t div_cl(uint32_t r, uint64_t M, int S) {
    return (uint32_t)(((uint64_t)r * M) >> S);
}

// Warp-specialized persistent single-pass fp16 kernel.
// Consumers (warps 0-15): 32x32 tiles, MMA + STG. Producers (16-23): LDG +
// fp16 cvt + swizzled STS into a 4-deep X ring. Balanced contiguous split.
__global__ __launch_bounds__(THREADS, 1)
void tp_f16(const float* __restrict__ x,
            const float* __restrict__ w,
            const float* __restrict__ pw,
            float* __restrict__ out,
            int n_nodes, int4 cum)
{
    extern __shared__ __align__(128) char smem[];
    const uint32_t sb = smem_u32(smem);

    const int tid  = threadIdx.x;
    const int lane = tid & 31;
    const int warp = tid >> 5;

    const int T  = cum.w;
    const int t0 = (int)(((long long)blockIdx.x * T) / gridDim.x);
    const int t1 = (int)(((long long)(blockIdx.x + 1) * T) / gridDim.x);
    if (t0 >= t1) return;

    auto l_of = [&](int g) {
        return (g < cum.x) ? 0 : (g < cum.y) ? 1 : (g < cum.z) ? 2 : 3;
    };
    const int l_first = l_of(t0);
    const int l_last  = l_of(t1 - 1);

    // consumer lane decomposition (32x32 warp tile)
    const int wr = warp & 3;
    const int wc = warp >> 2;
    const int a_hi = lane >> 4;
    int a_row[2], a_s[2];
    #pragma unroll
    for (int mt = 0; mt < 2; mt++) {
        a_row[mt] = wr * 32 + mt * 16 + (lane & 15);
        a_s[mt]   = a_row[mt] & 7;
    }
    const int bg   = lane >> 3;
    const int b_hi = bg & 1;
    int b_row[2], b_s[2];
    #pragma unroll
    for (int nt = 0; nt < 2; nt++) {
        b_row[nt] = wc * 32 + nt * 16 + ((bg >> 1) * 8) + (lane & 7);
        b_s[nt]   = b_row[nt] & 7;
    }
    const int grp = lane >> 2;
    const int qid = lane & 3;

    const int ptid  = tid - 512;
    const int my_lr = ptid >> 5;
    const int my_v  = ptid & 31;
    const float4* x4 = (const float4*)x;

    for (int l = l_first; l <= l_last; l++) {
        const int cp = (l == 0) ? 0 : (l == 1) ? cum.x : (l == 2) ? cum.y : cum.z;
        const int ce = (l == 0) ? cum.x : (l == 1) ? cum.y : (l == 2) ? cum.z : cum.w;
        int s0 = t0 > cp ? t0 : cp;
        int s1 = t1 < ce ? t1 : ce;
        if (s0 >= s1) continue;
        const int n = s1 - s0;

        const int cl     = 2 * l + 1;
        const int mbase  = l * l;
        const int rows_l = n_nodes * cl;
        const uint64_t M = (l == 0) ? 1ull : (l == 1) ? 0xAAAAAAABull
                         : (l == 2) ? 0xCCCCCCCDull : 0x92492493ull;
        const int S = (l == 0) ? 0 : (l == 1) ? 33 : 34;

        // ---- stage W[l]*pw -> fp16 [n][k] swizzled (all threads) ----
        __syncthreads();
        {
            const float scale = __ldg(&pw[l]);
            const float* wp = w + (size_t)l * C_DIM * C_DIM;
            #pragma unroll
            for (int e = tid; e < C_DIM * C_DIM; e += THREADS) {
                int k = e >> 7, nn = e & 127;
                __half h = __float2half_rn(wp[e] * scale);
                *(__half*)(smem + OFF_W + swz_off(nn, k)) = h;
            }
        }
        __syncthreads();

        if (warp >= 16) {
            // ================= PRODUCER =================
            for (int i = 0; i < n; i++) {
                const int p = i & (NBUF - 1);
                const int row0 = (s0 + i - cp) * BM;
                const uint32_t xb = XBUF(p);
                #pragma unroll
                for (int wave = 0; wave < 2; wave++) {
                    float4 v[8];
                    #pragma unroll
                    for (int c = 0; c < 8; c++) {
                        int lr = wave * 64 + c * 8 + my_lr;
                        int r  = row0 + lr;
                        v[c] = make_float4(0.f, 0.f, 0.f, 0.f);
                        if (r < rows_l) {
                            uint32_t node = div_cl((uint32_t)r, M, S);
                            uint32_t m    = (uint32_t)mbase + ((uint32_t)r - node * cl);
                            v[c] = __ldg(x4 + ((size_t)node * N_COMP + m) * 32 + my_v);
                        }
                    }
                    if (wave == 0 && i >= NBUF) bar_sync(5 + p);
                    #pragma unroll
                    for (int c = 0; c < 8; c++) {
                        int lr = wave * 64 + c * 8 + my_lr;
                        uint2 u;
                        __half2 h0 = __floats2half2_rn(v[c].x, v[c].y);
                        __half2 h1 = __floats2half2_rn(v[c].z, v[c].w);
                        u.x = *(uint32_t*)&h0;
                        u.y = *(uint32_t*)&h1;
                        *(uint2*)(smem + xb + swz_off(lr, my_v * 4)) = u;
                    }
                }
                bar_arrive(1 + p);
            }
        } else {
            // ================= CONSUMER =================
            for (int i = 0; i < n; i++) {
                const int p = i & (NBUF - 1);
                const int row0 = (s0 + i - cp) * BM;
                const uint32_t xb = sb + XBUF(p);

                bar_sync(1 + p);

                float acc[2][4][4];
                #pragma unroll
                for (int mt = 0; mt < 2; mt++)
                    #pragma unroll
                    for (int n8 = 0; n8 < 4; n8++)
                        #pragma unroll
                        for (int j = 0; j < 4; j++) acc[mt][n8][j] = 0.f;

                #pragma unroll
                for (int ks = 0; ks < 8; ks++) {
                    const uint32_t hoff = (ks & 4) ? HALF : 0u;
                    const int c0 = (ks & 3) * 2;

                    uint32_t A[2][4];
                    #pragma unroll
                    for (int mt = 0; mt < 2; mt++) {
                        uint32_t a = xb + hoff + (uint32_t)(a_row[mt] << 7)
                                   + (uint32_t)((((c0 | a_hi) ^ a_s[mt])) << 4);
                        ldmx4(A[mt][0], A[mt][1], A[mt][2], A[mt][3], a);
                    }
                    uint32_t B[2][4];
                    #pragma unroll
                    for (int nt = 0; nt < 2; nt++) {
                        uint32_t b = sb + OFF_W + hoff
                                   + (uint32_t)(b_row[nt] << 7)
                                   + (uint32_t)((((c0 | b_hi) ^ b_s[nt])) << 4);
                        ldmx4(B[nt][0], B[nt][1], B[nt][2], B[nt][3], b);
                    }
                    #pragma unroll
                    for (int mt = 0; mt < 2; mt++)
                        #pragma unroll
                        for (int n8 = 0; n8 < 4; n8++) {
                            const int nt = n8 >> 1, q = (n8 & 1) * 2;
                            mma_f16(acc[mt][n8], A[mt], B[nt][q], B[nt][q + 1]);
                        }
                }

                // free buffer p (skip last NBUF tiles to keep barriers drained)
                if (i + NBUF + 1 <= n) bar_arrive(5 + p);

                // ---- epilogue ----
                #pragma unroll
                for (int mt = 0; mt < 2; mt++) {
                    #pragma unroll
                    for (int h = 0; h < 2; h++) {
                        int r = row0 + wr * 32 + mt * 16 + grp + h * 8;
                        if (r < rows_l) {
                            uint32_t node = div_cl((uint32_t)r, M, S);
                            uint32_t m    = (uint32_t)mbase + ((uint32_t)r - node * cl);
                            float* orow = out + ((size_t)node * N_COMP + m) * C_DIM
                                              + wc * 32 + qid * 2;
                            #pragma unroll
                            for (int n8 = 0; n8 < 4; n8++) {
                                float2 v2 = make_float2(acc[mt][n8][h * 2],
                                                        acc[mt][n8][h * 2 + 1]);
                                *(float2*)(orow + n8 * 8) = v2;
                            }
                        }
                    }
                }
            }
        }
    }
}

extern "C" void kernel_launch(void* const* d_in, const int* in_sizes, int n_in,
                              void* d_out, int out_size) {
    const float* x  = (const float*)d_in[0];
    const float* w  = (const float*)d_in[1];
    const float* pw = (const float*)d_in[2];
    float* out = (float*)d_out;

    const int n_nodes = in_sizes[0] / (N_COMP * C_DIM);

    int dev = 0, nsm = 148;
    cudaGetDevice(&dev);
    cudaDeviceGetAttribute(&nsm, cudaDevAttrMultiProcessorCount, dev);

    int t[4];
    int4 cum;
    for (int l = 0; l < 4; l++)
        t[l] = (n_nodes * (2 * l + 1) + BM - 1) / BM;
    cum.x = t[0];
    cum.y = cum.x + t[1];
    cum.z = cum.y + t[2];
    cum.w = cum.z + t[3];

    size_t smem_bytes = 163840;   // 160KB: 4x32KB X ring + 32KB W
    cudaFuncSetAttribute(tp_f16,
                         cudaFuncAttributeMaxDynamicSharedMemorySize,
                         (int)smem_bytes);

    tp_f16<<<nsm, THREADS, smem_bytes>>>(x, w, pw, out, n_nodes, cum);
}